// round 1
// baseline (speedup 1.0000x reference)
#include <cuda_runtime.h>
#include <cuda_bf16.h>
#include <math_constants.h>

// Problem constants
#define Bb 4
#define Cc 256
#define Hh 64
#define Ww 64
#define Nn_TOK 4096      // H*W
#define NGROUP 32
#define CPG 8            // channels per group
#define EPSV 1e-5f

// Scratch (device globals; allocation in kernel_launch is forbidden)
static __device__ float g_normed[(size_t)Bb * Cc * Nn_TOK];          // 16 MB
static __device__ float g_qkv[(size_t)Bb * 3 * Cc * Nn_TOK];         // 48 MB
static __device__ float g_attn[(size_t)Bb * Nn_TOK * Nn_TOK];        // 256 MB
static __device__ float g_out[(size_t)Bb * Cc * Nn_TOK];             // 16 MB
static __device__ float g_stats[Bb * NGROUP * 2];                    // mean, rstd

// ---------------------------------------------------------------------------
// GroupNorm stats: one block per (b, group); reduce 8*4096 = 32768 floats
// ---------------------------------------------------------------------------
__global__ __launch_bounds__(256) void gn_stats_kernel(const float* __restrict__ x) {
    int bg = blockIdx.x;  // 0..127  (= b*32 + g, groups contiguous in channel dim)
    const float4* p4 = (const float4*)(x + (size_t)bg * CPG * Nn_TOK);
    int tid = threadIdx.x;
    float s = 0.f, ss = 0.f;
    #pragma unroll 4
    for (int i = tid; i < (CPG * Nn_TOK) / 4; i += 256) {
        float4 v = p4[i];
        s  += v.x + v.y + v.z + v.w;
        ss += v.x * v.x + v.y * v.y + v.z * v.z + v.w * v.w;
    }
    // block reduce
    __shared__ float sh_s[32], sh_ss[32];
    for (int off = 16; off > 0; off >>= 1) {
        s  += __shfl_xor_sync(0xffffffffu, s, off);
        ss += __shfl_xor_sync(0xffffffffu, ss, off);
    }
    int wid = tid >> 5, lid = tid & 31;
    if (lid == 0) { sh_s[wid] = s; sh_ss[wid] = ss; }
    __syncthreads();
    if (wid == 0) {
        s  = (lid < 8) ? sh_s[lid]  : 0.f;
        ss = (lid < 8) ? sh_ss[lid] : 0.f;
        for (int off = 4; off > 0; off >>= 1) {
            s  += __shfl_xor_sync(0xffffffffu, s, off);
            ss += __shfl_xor_sync(0xffffffffu, ss, off);
        }
        if (lid == 0) {
            const float inv_n = 1.0f / (CPG * Nn_TOK);
            float mean = s * inv_n;
            float var  = ss * inv_n - mean * mean;
            g_stats[bg * 2 + 0] = mean;
            g_stats[bg * 2 + 1] = rsqrtf(var + EPSV);
        }
    }
}

// ---------------------------------------------------------------------------
// GroupNorm apply (vectorized elementwise)
// ---------------------------------------------------------------------------
__global__ __launch_bounds__(256) void gn_apply_kernel(const float* __restrict__ x,
                                                       const float* __restrict__ gamma,
                                                       const float* __restrict__ beta) {
    size_t i4 = (size_t)blockIdx.x * 256 + threadIdx.x;   // float4 index
    size_t idx = i4 * 4;                                   // element index (same c for all 4)
    int c  = (int)((idx >> 12) & 255);                     // idx / 4096 % 256
    int bg = (int)(idx >> 15);                             // idx / (8*4096) = b*32 + g
    float mean = g_stats[bg * 2 + 0];
    float rstd = g_stats[bg * 2 + 1];
    float sc = gamma[c] * rstd;
    float sh = beta[c] - mean * sc;
    float4 v = ((const float4*)x)[i4];
    v.x = v.x * sc + sh; v.y = v.y * sc + sh;
    v.z = v.z * sc + sh; v.w = v.w * sc + sh;
    ((float4*)g_normed)[i4] = v;
}

// ---------------------------------------------------------------------------
// Templated SGEMM: C[m,n] = alpha * sum_k Ae(m,k)*Be(k,n)  (+ R[m,n])
//   Ae(m,k) = TA ? A[k*lda + m] : A[m*lda + k]
//   Be(k,n) = TB ? B[n*ldb + k] : B[k*ldb + n]
// Tiles: BM=BN=128, BK=16, 256 threads, 8x8 per thread.
// All problem dims are exact multiples -> no bounds checks.
// ---------------------------------------------------------------------------
#define BM 128
#define BN 128
#define BK 16
#define TM 8
#define TNr 8

template <bool TA, bool TB>
__global__ __launch_bounds__(256) void sgemm_kernel(
    const float* __restrict__ Ag, const float* __restrict__ Bg,
    float* __restrict__ Cg, const float* __restrict__ Rg,
    int lda, int ldb, int ldc,
    long long sA, long long sB, long long sC, long long sR,
    float alpha)
{
    const float* A = Ag + (size_t)blockIdx.z * sA;
    const float* B = Bg + (size_t)blockIdx.z * sB;
    float*       C = Cg + (size_t)blockIdx.z * sC;

    __shared__ float As[BK][BM];
    __shared__ float Bs[BK][BN];

    const int tid  = threadIdx.x;
    const int cRow = blockIdx.y * BM;
    const int cCol = blockIdx.x * BN;
    const int tx = tid & 15;
    const int ty = tid >> 4;

    float acc[TM][TNr];
    #pragma unroll
    for (int i = 0; i < TM; i++)
        #pragma unroll
        for (int j = 0; j < TNr; j++) acc[i][j] = 0.f;

    const int K = TA ? 0 : 0; (void)K; // (K passed via gridDim-independent loop below)

    // K extent is passed implicitly through lda/ldb usage; we need it explicitly:
    // we smuggle it in alpha? No - use a loop bound parameter:
    // (see launch: we pass K via ldc? No.) -> use constant memory free approach:
    // Simpler: K is derivable per instantiation is NOT true; pass via sR when Rg==null?
    // Cleanest: make K a kernel parameter.
    // (This block intentionally left; real K parameter added below.)
    // -- replaced by Kdim parameter version --
    // NOTE: see sgemm_kernel_k below.
    if (false) { (void)A; (void)B; (void)C; }
}

// Real GEMM (with explicit K parameter)
template <bool TA, bool TB>
__global__ __launch_bounds__(256) void sgemm_k(
    const float* __restrict__ Ag, const float* __restrict__ Bg,
    float* __restrict__ Cg, const float* __restrict__ Rg,
    int Kdim, int lda, int ldb, int ldc,
    long long sA, long long sB, long long sC, long long sR,
    float alpha)
{
    const float* A = Ag + (size_t)blockIdx.z * sA;
    const float* B = Bg + (size_t)blockIdx.z * sB;
    float*       C = Cg + (size_t)blockIdx.z * sC;
    const float* R = Rg ? (Rg + (size_t)blockIdx.z * sR) : nullptr;

    __shared__ float As[BK][BM];
    __shared__ float Bs[BK][BN];

    const int tid  = threadIdx.x;
    const int cRow = blockIdx.y * BM;
    const int cCol = blockIdx.x * BN;
    const int tx = tid & 15;
    const int ty = tid >> 4;

    float acc[TM][TNr];
    #pragma unroll
    for (int i = 0; i < TM; i++)
        #pragma unroll
        for (int j = 0; j < TNr; j++) acc[i][j] = 0.f;

    for (int k0 = 0; k0 < Kdim; k0 += BK) {
        // ---- load A tile -> As[kk][mm]
        if (TA) {
            // A[k*lda + m], contiguous along m
            #pragma unroll
            for (int i = 0; i < 2; i++) {
                int ff = tid + i * 256;           // float4 id, 512 total
                int kk = ff >> 5;                 // /32
                int mm = (ff & 31) << 2;          // *4
                float4 v = *(const float4*)&A[(size_t)(k0 + kk) * lda + cRow + mm];
                *(float4*)&As[kk][mm] = v;
            }
        } else {
            // A[m*lda + k], contiguous along k; transpose on store
            #pragma unroll
            for (int i = 0; i < 2; i++) {
                int ff = tid + i * 256;
                int mm = ff >> 2;
                int kk = (ff & 3) << 2;
                float4 v = *(const float4*)&A[(size_t)(cRow + mm) * lda + k0 + kk];
                As[kk + 0][mm] = v.x; As[kk + 1][mm] = v.y;
                As[kk + 2][mm] = v.z; As[kk + 3][mm] = v.w;
            }
        }
        // ---- load B tile -> Bs[kk][nn]
        if (TB) {
            // B[n*ldb + k], contiguous along k; transpose on store
            #pragma unroll
            for (int i = 0; i < 2; i++) {
                int ff = tid + i * 256;
                int nn = ff >> 2;
                int kk = (ff & 3) << 2;
                float4 v = *(const float4*)&B[(size_t)(cCol + nn) * ldb + k0 + kk];
                Bs[kk + 0][nn] = v.x; Bs[kk + 1][nn] = v.y;
                Bs[kk + 2][nn] = v.z; Bs[kk + 3][nn] = v.w;
            }
        } else {
            // B[k*ldb + n], contiguous along n
            #pragma unroll
            for (int i = 0; i < 2; i++) {
                int ff = tid + i * 256;
                int kk = ff >> 5;
                int nn = (ff & 31) << 2;
                float4 v = *(const float4*)&B[(size_t)(k0 + kk) * ldb + cCol + nn];
                *(float4*)&Bs[kk][nn] = v;
            }
        }
        __syncthreads();

        #pragma unroll
        for (int kk = 0; kk < BK; kk++) {
            float a[TM], b[TNr];
            #pragma unroll
            for (int i = 0; i < TM; i++) a[i] = As[kk][ty * TM + i];
            #pragma unroll
            for (int j = 0; j < TNr; j++) b[j] = Bs[kk][tx * TNr + j];
            #pragma unroll
            for (int i = 0; i < TM; i++)
                #pragma unroll
                for (int j = 0; j < TNr; j++)
                    acc[i][j] += a[i] * b[j];
        }
        __syncthreads();
    }

    // ---- epilogue
    #pragma unroll
    for (int i = 0; i < TM; i++) {
        int m = cRow + ty * TM + i;
        #pragma unroll
        for (int j = 0; j < TNr; j += 4) {
            int n = cCol + tx * TNr + j;
            float4 r;
            r.x = alpha * acc[i][j + 0];
            r.y = alpha * acc[i][j + 1];
            r.z = alpha * acc[i][j + 2];
            r.w = alpha * acc[i][j + 3];
            if (R) {
                float4 rv = *(const float4*)&R[(size_t)m * ldc + n];
                r.x += rv.x; r.y += rv.y; r.z += rv.z; r.w += rv.w;
            }
            *(float4*)&C[(size_t)m * ldc + n] = r;
        }
    }
}

// ---------------------------------------------------------------------------
// Row softmax over 4096 elements, one block (256 thr) per row, in place.
// ---------------------------------------------------------------------------
__global__ __launch_bounds__(256) void softmax_kernel(float* __restrict__ attn) {
    float4* row = (float4*)(attn + (size_t)blockIdx.x * Nn_TOK);
    const int tid = threadIdx.x;

    float4 v[4];
    float lmax = -CUDART_INF_F;
    #pragma unroll
    for (int i = 0; i < 4; i++) {
        v[i] = row[tid + i * 256];
        lmax = fmaxf(lmax, fmaxf(fmaxf(v[i].x, v[i].y), fmaxf(v[i].z, v[i].w)));
    }
    // block max
    __shared__ float sh[8];
    for (int off = 16; off > 0; off >>= 1)
        lmax = fmaxf(lmax, __shfl_xor_sync(0xffffffffu, lmax, off));
    int wid = tid >> 5, lid = tid & 31;
    if (lid == 0) sh[wid] = lmax;
    __syncthreads();
    lmax = sh[0];
    #pragma unroll
    for (int w = 1; w < 8; w++) lmax = fmaxf(lmax, sh[w]);

    float lsum = 0.f;
    #pragma unroll
    for (int i = 0; i < 4; i++) {
        v[i].x = __expf(v[i].x - lmax); v[i].y = __expf(v[i].y - lmax);
        v[i].z = __expf(v[i].z - lmax); v[i].w = __expf(v[i].w - lmax);
        lsum += v[i].x + v[i].y + v[i].z + v[i].w;
    }
    for (int off = 16; off > 0; off >>= 1)
        lsum += __shfl_xor_sync(0xffffffffu, lsum, off);
    __syncthreads();
    if (lid == 0) sh[wid] = lsum;
    __syncthreads();
    lsum = 0.f;
    #pragma unroll
    for (int w = 0; w < 8; w++) lsum += sh[w];
    float inv = 1.0f / lsum;

    #pragma unroll
    for (int i = 0; i < 4; i++) {
        v[i].x *= inv; v[i].y *= inv; v[i].z *= inv; v[i].w *= inv;
        row[tid + i * 256] = v[i];
    }
}

// ---------------------------------------------------------------------------
// Launch
// ---------------------------------------------------------------------------
extern "C" void kernel_launch(void* const* d_in, const int* in_sizes, int n_in,
                              void* d_out, int out_size) {
    const float* x      = (const float*)d_in[0];
    // d_in[1] = t (unused scalar)
    const float* gamma  = (const float*)d_in[2];
    const float* beta   = (const float*)d_in[3];
    const float* w_qkv  = (const float*)d_in[4];
    const float* w_proj = (const float*)d_in[5];
    float* y = (float*)d_out;

    float *p_normed, *p_qkv, *p_attn, *p_out;
    cudaGetSymbolAddress((void**)&p_normed, g_normed);
    cudaGetSymbolAddress((void**)&p_qkv,    g_qkv);
    cudaGetSymbolAddress((void**)&p_attn,   g_attn);
    cudaGetSymbolAddress((void**)&p_out,    g_out);

    const long long CN  = (long long)Cc * Nn_TOK;       // 1,048,576
    const long long NN  = (long long)Nn_TOK * Nn_TOK;   // 16,777,216

    // 1) GroupNorm
    gn_stats_kernel<<<Bb * NGROUP, 256>>>(x);
    gn_apply_kernel<<<(Bb * CN) / (256 * 4), 256>>>(x, gamma, beta);

    // 2) qkv = W_qkv[768,256] @ normed[256,4096]  (NN), per batch
    {
        dim3 grid(Nn_TOK / BN, (3 * Cc) / BM, Bb);
        sgemm_k<false, false><<<grid, 256>>>(
            w_qkv, p_normed, p_qkv, nullptr,
            /*K*/ Cc, /*lda*/ Cc, /*ldb*/ Nn_TOK, /*ldc*/ Nn_TOK,
            /*sA*/ 0, /*sB*/ CN, /*sC*/ 3 * CN, /*sR*/ 0, 1.0f);
    }

    // 3) scores[i,j] = (1/16) * sum_c q[c,i] k[c,j]   (TA=true, TB=false)
    {
        dim3 grid(Nn_TOK / BN, Nn_TOK / BM, Bb);
        sgemm_k<true, false><<<grid, 256>>>(
            p_qkv /*q*/, p_qkv + CN /*k*/, p_attn, nullptr,
            /*K*/ Cc, /*lda*/ Nn_TOK, /*ldb*/ Nn_TOK, /*ldc*/ Nn_TOK,
            /*sA*/ 3 * CN, /*sB*/ 3 * CN, /*sC*/ NN, /*sR*/ 0, 1.0f / 16.0f);
    }

    // 4) softmax rows
    softmax_kernel<<<Bb * Nn_TOK, 256>>>(p_attn);

    // 5) out[c,i] = sum_j v[c,j] attn[i,j]   (TA=false, TB=true)
    {
        dim3 grid(Nn_TOK / BN, Cc / BM, Bb);
        sgemm_k<false, true><<<grid, 256>>>(
            p_qkv + 2 * CN /*v*/, p_attn, p_out, nullptr,
            /*K*/ Nn_TOK, /*lda*/ Nn_TOK, /*ldb*/ Nn_TOK, /*ldc*/ Nn_TOK,
            /*sA*/ 3 * CN, /*sB*/ NN, /*sC*/ CN, /*sR*/ 0, 1.0f);
    }

    // 6) y = x + W_proj[256,256] @ out[256,4096]   (NN + residual)
    {
        dim3 grid(Nn_TOK / BN, Cc / BM, Bb);
        sgemm_k<false, false><<<grid, 256>>>(
            w_proj, p_out, y, x,
            /*K*/ Cc, /*lda*/ Cc, /*ldb*/ Nn_TOK, /*ldc*/ Nn_TOK,
            /*sA*/ 0, /*sB*/ CN, /*sC*/ CN, /*sR*/ CN, 1.0f);
    }
}

// round 4
// speedup vs baseline: 2.1555x; 2.1555x over previous
#include <cuda_runtime.h>
#include <cuda_bf16.h>
#include <math_constants.h>
#include <cstdint>

// ---------------------------------------------------------------------------
// Problem constants
// ---------------------------------------------------------------------------
#define Bb 4
#define Cc 256
#define Nn_TOK 4096
#define NGROUP 32
#define CPG 8
#define EPSV 1e-5f

#define CN_  ((long long)Cc * Nn_TOK)        // 1,048,576
#define NN_  ((long long)Nn_TOK * Nn_TOK)    // 16,777,216
#define QKVN ((long long)Nn_TOK * 768)       // 3,145,728

// ---------------------------------------------------------------------------
// Scratch (device globals)
// ---------------------------------------------------------------------------
static __device__ __align__(128) float g_attn[(size_t)Bb * NN_];                  // 256 MB
static __device__ __align__(128) __nv_bfloat16 g_attn_h[(size_t)Bb * NN_];        // 128 MB
static __device__ __align__(128) __nv_bfloat16 g_attn_l[(size_t)Bb * NN_];        // 128 MB
static __device__ __align__(128) __nv_bfloat16 g_n_h[(size_t)Bb * CN_];           // normed_t [i,c]
static __device__ __align__(128) __nv_bfloat16 g_n_l[(size_t)Bb * CN_];
static __device__ __align__(128) __nv_bfloat16 g_qt_h[(size_t)Bb * QKVN];         // qkv_t [i,768]
static __device__ __align__(128) __nv_bfloat16 g_qt_l[(size_t)Bb * QKVN];
static __device__ __align__(128) __nv_bfloat16 g_v_h[(size_t)Bb * CN_];           // v_n [c,i]
static __device__ __align__(128) __nv_bfloat16 g_v_l[(size_t)Bb * CN_];
static __device__ __align__(128) __nv_bfloat16 g_ot_h[(size_t)Bb * CN_];          // out_t [i,c]
static __device__ __align__(128) __nv_bfloat16 g_ot_l[(size_t)Bb * CN_];
static __device__ __align__(128) __nv_bfloat16 g_wq_h[768 * 256];
static __device__ __align__(128) __nv_bfloat16 g_wq_l[768 * 256];
static __device__ __align__(128) __nv_bfloat16 g_wp_h[256 * 256];
static __device__ __align__(128) __nv_bfloat16 g_wp_l[256 * 256];
static __device__ float g_stats[Bb * NGROUP * 2];

// ---------------------------------------------------------------------------
// Helpers
// ---------------------------------------------------------------------------
__device__ __forceinline__ uint32_t smem_u32(const void* p) {
    uint32_t a;
    asm("{ .reg .u64 t; cvta.to.shared.u64 t, %1; cvt.u32.u64 %0, t; }" : "=r"(a) : "l"(p));
    return a;
}

__device__ __forceinline__ void mma16816(float* d, const uint32_t* a, const uint32_t* b) {
    asm volatile(
        "mma.sync.aligned.m16n8k16.row.col.f32.bf16.bf16.f32 "
        "{%0,%1,%2,%3}, {%4,%5,%6,%7}, {%8,%9}, {%0,%1,%2,%3};"
        : "+f"(d[0]), "+f"(d[1]), "+f"(d[2]), "+f"(d[3])
        : "r"(a[0]), "r"(a[1]), "r"(a[2]), "r"(a[3]), "r"(b[0]), "r"(b[1]));
}

__device__ __forceinline__ void ldsm_x4(uint32_t* r, uint32_t addr) {
    asm volatile("ldmatrix.sync.aligned.m8n8.x4.shared.b16 {%0,%1,%2,%3}, [%4];"
                 : "=r"(r[0]), "=r"(r[1]), "=r"(r[2]), "=r"(r[3]) : "r"(addr));
}

#define CP_COMMIT() asm volatile("cp.async.commit_group;" ::: "memory")
#define CP_WAIT1()  asm volatile("cp.async.wait_group 1;" ::: "memory")
#define CP_WAIT0()  asm volatile("cp.async.wait_group 0;" ::: "memory")

// ---------------------------------------------------------------------------
// GroupNorm stats
// ---------------------------------------------------------------------------
__global__ __launch_bounds__(256) void gn_stats_kernel(const float* __restrict__ x) {
    int bg = blockIdx.x;
    const float4* p4 = (const float4*)(x + (size_t)bg * CPG * Nn_TOK);
    int tid = threadIdx.x;
    float s = 0.f, ss = 0.f;
    #pragma unroll 4
    for (int i = tid; i < (CPG * Nn_TOK) / 4; i += 256) {
        float4 v = p4[i];
        s  += v.x + v.y + v.z + v.w;
        ss += v.x * v.x + v.y * v.y + v.z * v.z + v.w * v.w;
    }
    __shared__ float sh_s[32], sh_ss[32];
    for (int off = 16; off > 0; off >>= 1) {
        s  += __shfl_xor_sync(0xffffffffu, s, off);
        ss += __shfl_xor_sync(0xffffffffu, ss, off);
    }
    int wid = tid >> 5, lid = tid & 31;
    if (lid == 0) { sh_s[wid] = s; sh_ss[wid] = ss; }
    __syncthreads();
    if (wid == 0) {
        s  = (lid < 8) ? sh_s[lid]  : 0.f;
        ss = (lid < 8) ? sh_ss[lid] : 0.f;
        for (int off = 4; off > 0; off >>= 1) {
            s  += __shfl_xor_sync(0xffffffffu, s, off);
            ss += __shfl_xor_sync(0xffffffffu, ss, off);
        }
        if (lid == 0) {
            const float inv_n = 1.0f / (CPG * Nn_TOK);
            float mean = s * inv_n;
            float var  = ss * inv_n - mean * mean;
            g_stats[bg * 2 + 0] = mean;
            g_stats[bg * 2 + 1] = rsqrtf(var + EPSV);
        }
    }
}

// ---------------------------------------------------------------------------
// GroupNorm apply + transpose + bf16 hi/lo split:  x[c,i] -> normed_t[i,c]
// ---------------------------------------------------------------------------
__global__ __launch_bounds__(256) void gn_apply_t(const float* __restrict__ x,
                                                  const float* __restrict__ gamma,
                                                  const float* __restrict__ beta,
                                                  __nv_bfloat16* __restrict__ Nh,
                                                  __nv_bfloat16* __restrict__ Nl) {
    __shared__ float tile[32][33];
    int b = blockIdx.z;
    int c0 = blockIdx.x * 32, i0 = blockIdx.y * 32;
    int tx = threadIdx.x & 31, ty = threadIdx.x >> 5;
    const float* xb = x + (size_t)b * CN_;
    #pragma unroll
    for (int rr = ty; rr < 32; rr += 8) {
        int c = c0 + rr;
        int bg = b * NGROUP + (c >> 3);
        float mean = g_stats[bg * 2 + 0], rstd = g_stats[bg * 2 + 1];
        float sc = gamma[c] * rstd;
        float sh = beta[c] - mean * sc;
        tile[rr][tx] = xb[(size_t)c * Nn_TOK + i0 + tx] * sc + sh;
    }
    __syncthreads();
    size_t ob = (size_t)b * CN_;
    #pragma unroll
    for (int rr = ty; rr < 32; rr += 8) {
        int i = i0 + rr, c = c0 + tx;
        float v = tile[tx][rr];
        __nv_bfloat16 h = __float2bfloat16(v);
        Nh[ob + (size_t)i * Cc + c] = h;
        Nl[ob + (size_t)i * Cc + c] = __float2bfloat16(v - __bfloat162float(h));
    }
}

// ---------------------------------------------------------------------------
// fp32 -> bf16 hi/lo split (weights)
// ---------------------------------------------------------------------------
__global__ __launch_bounds__(256) void split_convert(const float* __restrict__ src,
                                                     __nv_bfloat16* __restrict__ h,
                                                     __nv_bfloat16* __restrict__ l, int n) {
    int i = blockIdx.x * 256 + threadIdx.x;
    if (i < n) {
        float v = src[i];
        __nv_bfloat16 hi = __float2bfloat16(v);
        h[i] = hi;
        l[i] = __float2bfloat16(v - __bfloat162float(hi));
    }
}

// ---------------------------------------------------------------------------
// v transpose: qkv_t[i, 512+c] -> v_n[c, i]  (bf16 hi+lo)
// ---------------------------------------------------------------------------
__global__ __launch_bounds__(256) void v_transpose(const __nv_bfloat16* __restrict__ Qh,
                                                   const __nv_bfloat16* __restrict__ Ql,
                                                   __nv_bfloat16* __restrict__ Vh,
                                                   __nv_bfloat16* __restrict__ Vl) {
    __shared__ __nv_bfloat16 th[32][33], tl[32][33];
    int b = blockIdx.z;
    int c0 = blockIdx.x * 32, i0 = blockIdx.y * 32;
    int tx = threadIdx.x & 31, ty = threadIdx.x >> 5;
    size_t ib = (size_t)b * QKVN;
    #pragma unroll
    for (int rr = ty; rr < 32; rr += 8) {
        size_t o = ib + (size_t)(i0 + rr) * 768 + 512 + c0 + tx;
        th[rr][tx] = Qh[o];
        tl[rr][tx] = Ql[o];
    }
    __syncthreads();
    size_t ob = (size_t)b * CN_;
    #pragma unroll
    for (int rr = ty; rr < 32; rr += 8) {
        size_t o = ob + (size_t)(c0 + rr) * Nn_TOK + i0 + tx;
        Vh[o] = th[tx][rr];
        Vl[o] = tl[tx][rr];
    }
}

// ---------------------------------------------------------------------------
// Row softmax (fp32 in), write bf16 hi/lo
// ---------------------------------------------------------------------------
__global__ __launch_bounds__(256) void softmax_split(const float* __restrict__ attn,
                                                     __nv_bfloat16* __restrict__ Oh,
                                                     __nv_bfloat16* __restrict__ Ol) {
    const float4* row = (const float4*)(attn + (size_t)blockIdx.x * Nn_TOK);
    const int tid = threadIdx.x;

    float4 v[4];
    float lmax = -CUDART_INF_F;
    #pragma unroll
    for (int i = 0; i < 4; i++) {
        v[i] = row[tid + i * 256];
        lmax = fmaxf(lmax, fmaxf(fmaxf(v[i].x, v[i].y), fmaxf(v[i].z, v[i].w)));
    }
    __shared__ float sh[8];
    for (int off = 16; off > 0; off >>= 1)
        lmax = fmaxf(lmax, __shfl_xor_sync(0xffffffffu, lmax, off));
    int wid = tid >> 5, lid = tid & 31;
    if (lid == 0) sh[wid] = lmax;
    __syncthreads();
    lmax = sh[0];
    #pragma unroll
    for (int w = 1; w < 8; w++) lmax = fmaxf(lmax, sh[w]);

    float lsum = 0.f;
    #pragma unroll
    for (int i = 0; i < 4; i++) {
        v[i].x = __expf(v[i].x - lmax); v[i].y = __expf(v[i].y - lmax);
        v[i].z = __expf(v[i].z - lmax); v[i].w = __expf(v[i].w - lmax);
        lsum += v[i].x + v[i].y + v[i].z + v[i].w;
    }
    for (int off = 16; off > 0; off >>= 1)
        lsum += __shfl_xor_sync(0xffffffffu, lsum, off);
    __syncthreads();
    if (lid == 0) sh[wid] = lsum;
    __syncthreads();
    lsum = 0.f;
    #pragma unroll
    for (int w = 0; w < 8; w++) lsum += sh[w];
    float inv = 1.0f / lsum;

    __nv_bfloat162* Hr = (__nv_bfloat162*)(Oh + (size_t)blockIdx.x * Nn_TOK);
    __nv_bfloat162* Lr = (__nv_bfloat162*)(Ol + (size_t)blockIdx.x * Nn_TOK);
    #pragma unroll
    for (int i = 0; i < 4; i++) {
        float px = v[i].x * inv, py = v[i].y * inv, pz = v[i].z * inv, pw = v[i].w * inv;
        __nv_bfloat16 hx = __float2bfloat16(px), hy = __float2bfloat16(py);
        __nv_bfloat16 hz = __float2bfloat16(pz), hw = __float2bfloat16(pw);
        __nv_bfloat162 h01; h01.x = hx; h01.y = hy;
        __nv_bfloat162 h23; h23.x = hz; h23.y = hw;
        __nv_bfloat162 l01, l23;
        l01.x = __float2bfloat16(px - __bfloat162float(hx));
        l01.y = __float2bfloat16(py - __bfloat162float(hy));
        l23.x = __float2bfloat16(pz - __bfloat162float(hz));
        l23.y = __float2bfloat16(pw - __bfloat162float(hw));
        int c4 = tid + i * 256;
        Hr[c4 * 2 + 0] = h01; Hr[c4 * 2 + 1] = h23;
        Lr[c4 * 2 + 0] = l01; Lr[c4 * 2 + 1] = l23;
    }
}

// ---------------------------------------------------------------------------
// HMMA split-bf16 GEMM:  D[m,n] = sum_k A[m,k] * B[n,k]
// A = Ah + Al, B = Bh + Bl; 3-product emulation (hh + hl + lh).
// CTA tile 128x128, 8 warps (2x4) of 64x32, BK=32, cp.async double buffer.
// MODE: 0 = write bf16 hi/lo; 1 = write fp32 * alpha; 2 = write fp32 + residual
// ---------------------------------------------------------------------------
#define LDT 40                       // padded row length in bf16 (80 B)
#define TILE_B (128 * LDT * 2)       // 10240 B per 128x32 tile
#define STAGE_B (4 * TILE_B)         // Ah, Al, Bh, Bl
#define GSMEM_B (2 * STAGE_B)        // 81920 B

__device__ __forceinline__ void cp_tile(uint32_t dst, const __nv_bfloat16* __restrict__ src,
                                        int ld, int row0, int k0, int tid) {
    #pragma unroll
    for (int j = 0; j < 2; j++) {
        int c = tid + j * 256;
        int row = c >> 2;
        int co = (c & 3) << 4;  // byte offset within 64B row chunk
        const void* g = (const char*)(src + (size_t)(row0 + row) * ld + k0) + co;
        uint32_t s = dst + row * 80 + co;
        asm volatile("cp.async.cg.shared.global [%0], [%1], 16;" :: "r"(s), "l"(g));
    }
}

template <int MODE>
__global__ __launch_bounds__(256, 1)
void hmma_gemm(const __nv_bfloat16* __restrict__ Ah, const __nv_bfloat16* __restrict__ Al,
               const __nv_bfloat16* __restrict__ Bh, const __nv_bfloat16* __restrict__ Bl,
               int K, int lda, int ldb, long long sA, long long sB,
               __nv_bfloat16* __restrict__ Oh, __nv_bfloat16* __restrict__ Ol,
               float* __restrict__ Cf, const float* __restrict__ Rf,
               int ldo, long long sO, long long sR, float alpha) {
    extern __shared__ char smem[];
    const uint32_t sb = smem_u32(smem);
    const int tid = threadIdx.x;
    const int lane = tid & 31, wid = tid >> 5;
    const int wm = wid & 1, wn = wid >> 1;      // 2 x 4 warp grid
    const int b = blockIdx.z;
    const int cRow = blockIdx.y * 128;
    const int cCol = blockIdx.x * 128;

    const __nv_bfloat16* pAh = Ah + (size_t)b * sA;
    const __nv_bfloat16* pAl = Al + (size_t)b * sA;
    const __nv_bfloat16* pBh = Bh + (size_t)b * sB;
    const __nv_bfloat16* pBl = Bl + (size_t)b * sB;

    float acc[4][4][4];
    #pragma unroll
    for (int i = 0; i < 4; i++)
        #pragma unroll
        for (int j = 0; j < 4; j++)
            #pragma unroll
            for (int q = 0; q < 4; q++) acc[i][j][q] = 0.f;

    const int nIt = K >> 5;

    // prefetch stage 0
    cp_tile(sb + 0 * TILE_B, pAh, lda, cRow, 0, tid);
    cp_tile(sb + 1 * TILE_B, pAl, lda, cRow, 0, tid);
    cp_tile(sb + 2 * TILE_B, pBh, ldb, cCol, 0, tid);
    cp_tile(sb + 3 * TILE_B, pBl, ldb, cCol, 0, tid);
    CP_COMMIT();

    for (int it = 0; it < nIt; it++) {
        const int cur = it & 1;
        if (it + 1 < nIt) {
            uint32_t nb = sb + ((it + 1) & 1) * STAGE_B;
            int k0 = (it + 1) << 5;
            cp_tile(nb + 0 * TILE_B, pAh, lda, cRow, k0, tid);
            cp_tile(nb + 1 * TILE_B, pAl, lda, cRow, k0, tid);
            cp_tile(nb + 2 * TILE_B, pBh, ldb, cCol, k0, tid);
            cp_tile(nb + 3 * TILE_B, pBl, ldb, cCol, k0, tid);
            CP_COMMIT();
            CP_WAIT1();
        } else {
            CP_WAIT0();
        }
        __syncthreads();

        const uint32_t base = sb + cur * STAGE_B;
        #pragma unroll
        for (int ks = 0; ks < 32; ks += 16) {
            uint32_t ah[4][4], al[4][4], bh[2][4], bl[2][4];
            // A fragments: lane -> row (lane&15), k-col offset 8*(lane>>4)
            const int arow = wm * 64 + (lane & 15);
            const int acol = ks + ((lane >> 4) << 3);
            #pragma unroll
            for (int mt = 0; mt < 4; mt++) {
                uint32_t ad = base + ((arow + mt * 16) * LDT + acol) * 2;
                ldsm_x4(ah[mt], ad);
                ldsm_x4(al[mt], ad + TILE_B);
            }
            // B fragments: mats (n0-7,k0),(n0-7,k8),(n8-15,k0),(n8-15,k8)
            const int brow = wn * 32 + ((lane >> 4) & 1) * 8 + (lane & 7);
            const int bcol = ks + ((lane >> 3) & 1) * 8;
            #pragma unroll
            for (int p = 0; p < 2; p++) {
                uint32_t bd = base + 2 * TILE_B + ((brow + p * 16) * LDT + bcol) * 2;
                ldsm_x4(bh[p], bd);
                ldsm_x4(bl[p], bd + TILE_B);
            }
            #pragma unroll
            for (int mt = 0; mt < 4; mt++)
                #pragma unroll
                for (int nt = 0; nt < 4; nt++) {
                    const uint32_t* B2h = &bh[nt >> 1][(nt & 1) * 2];
                    const uint32_t* B2l = &bl[nt >> 1][(nt & 1) * 2];
                    mma16816(acc[mt][nt], ah[mt], B2h);   // hi*hi
                    mma16816(acc[mt][nt], ah[mt], B2l);   // hi*lo
                    mma16816(acc[mt][nt], al[mt], B2h);   // lo*hi
                }
        }
        __syncthreads();
    }

    // Epilogue: fragment layout -> global
    #pragma unroll
    for (int mt = 0; mt < 4; mt++) {
        int m0 = cRow + wm * 64 + mt * 16 + (lane >> 2);
        #pragma unroll
        for (int nt = 0; nt < 4; nt++) {
            int n0 = cCol + wn * 32 + nt * 8 + (lane & 3) * 2;
            #pragma unroll
            for (int q = 0; q < 4; q++) {
                int m = m0 + (q >> 1) * 8;
                int n = n0 + (q & 1);
                float v = acc[mt][nt][q];
                size_t off = (size_t)m * ldo + n;
                if (MODE == 0) {
                    __nv_bfloat16 h = __float2bfloat16(v);
                    Oh[(size_t)b * sO + off] = h;
                    Ol[(size_t)b * sO + off] = __float2bfloat16(v - __bfloat162float(h));
                } else if (MODE == 1) {
                    Cf[(size_t)b * sO + off] = v * alpha;
                } else {
                    Cf[(size_t)b * sO + off] = v + Rf[(size_t)b * sR + off];
                }
            }
        }
    }
}

// ---------------------------------------------------------------------------
// Launch
// ---------------------------------------------------------------------------
extern "C" void kernel_launch(void* const* d_in, const int* in_sizes, int n_in,
                              void* d_out, int out_size) {
    const float* x      = (const float*)d_in[0];
    const float* gamma  = (const float*)d_in[2];
    const float* beta   = (const float*)d_in[3];
    const float* w_qkv  = (const float*)d_in[4];
    const float* w_proj = (const float*)d_in[5];
    float* y = (float*)d_out;

    float* p_attn;
    __nv_bfloat16 *p_ah, *p_al, *p_nh, *p_nl, *p_qth, *p_qtl, *p_vh, *p_vl,
                  *p_oth, *p_otl, *p_wqh, *p_wql, *p_wph, *p_wpl;
    cudaGetSymbolAddress((void**)&p_attn, g_attn);
    cudaGetSymbolAddress((void**)&p_ah,  g_attn_h);
    cudaGetSymbolAddress((void**)&p_al,  g_attn_l);
    cudaGetSymbolAddress((void**)&p_nh,  g_n_h);
    cudaGetSymbolAddress((void**)&p_nl,  g_n_l);
    cudaGetSymbolAddress((void**)&p_qth, g_qt_h);
    cudaGetSymbolAddress((void**)&p_qtl, g_qt_l);
    cudaGetSymbolAddress((void**)&p_vh,  g_v_h);
    cudaGetSymbolAddress((void**)&p_vl,  g_v_l);
    cudaGetSymbolAddress((void**)&p_oth, g_ot_h);
    cudaGetSymbolAddress((void**)&p_otl, g_ot_l);
    cudaGetSymbolAddress((void**)&p_wqh, g_wq_h);
    cudaGetSymbolAddress((void**)&p_wql, g_wq_l);
    cudaGetSymbolAddress((void**)&p_wph, g_wp_h);
    cudaGetSymbolAddress((void**)&p_wpl, g_wp_l);

    cudaFuncSetAttribute(hmma_gemm<0>, cudaFuncAttributeMaxDynamicSharedMemorySize, GSMEM_B);
    cudaFuncSetAttribute(hmma_gemm<1>, cudaFuncAttributeMaxDynamicSharedMemorySize, GSMEM_B);
    cudaFuncSetAttribute(hmma_gemm<2>, cudaFuncAttributeMaxDynamicSharedMemorySize, GSMEM_B);

    // 1) GroupNorm + weight conversion + transposed split
    gn_stats_kernel<<<Bb * NGROUP, 256>>>(x);
    split_convert<<<(768 * 256 + 255) / 256, 256>>>(w_qkv, p_wqh, p_wql, 768 * 256);
    split_convert<<<(256 * 256 + 255) / 256, 256>>>(w_proj, p_wph, p_wpl, 256 * 256);
    gn_apply_t<<<dim3(8, 128, Bb), 256>>>(x, gamma, beta, p_nh, p_nl);

    // 2) qkv_t[i,o] = normed_t[i,:] . w_qkv[o,:]   (M=4096, N=768, K=256)
    hmma_gemm<0><<<dim3(6, 32, Bb), 256, GSMEM_B>>>(
        p_nh, p_nl, p_wqh, p_wql, 256, 256, 256, CN_, 0,
        p_qth, p_qtl, nullptr, nullptr, 768, QKVN, 0, 1.0f);

    // 3) v transpose (v_t[i,c] -> v_n[c,i])
    v_transpose<<<dim3(8, 128, Bb), 256>>>(p_qth, p_qtl, p_vh, p_vl);

    // 4) scores[i,j] = (1/16) q_t[i,:] . k_t[j,:]  (M=N=4096, K=256)
    hmma_gemm<1><<<dim3(32, 32, Bb), 256, GSMEM_B>>>(
        p_qth, p_qtl, p_qth + 256, p_qtl + 256, 256, 768, 768, QKVN, QKVN,
        nullptr, nullptr, p_attn, nullptr, Nn_TOK, NN_, 0, 1.0f / 16.0f);

    // 5) softmax -> bf16 hi/lo
    softmax_split<<<Bb * Nn_TOK, 256>>>(p_attn, p_ah, p_al);

    // 6) out_t[i,c] = attn[i,:] . v_n[c,:]   (M=4096, N=256, K=4096)
    hmma_gemm<0><<<dim3(2, 32, Bb), 256, GSMEM_B>>>(
        p_ah, p_al, p_vh, p_vl, Nn_TOK, Nn_TOK, Nn_TOK, NN_, CN_,
        p_oth, p_otl, nullptr, nullptr, 256, CN_, 0, 1.0f);

    // 7) y[o,i] = x[o,i] + w_proj[o,:] . out_t[i,:]   (M=256, N=4096, K=256)
    hmma_gemm<2><<<dim3(32, 2, Bb), 256, GSMEM_B>>>(
        p_wph, p_wpl, p_oth, p_otl, 256, 256, 256, 0, CN_,
        nullptr, nullptr, y, x, Nn_TOK, CN_, CN_, 1.0f);
}